// round 10
// baseline (speedup 1.0000x reference)
#include <cuda_runtime.h>
#include <math.h>

// Problem constants (fixed by setup_inputs)
#define E_TOT   32768          // B*N*K = 1*1024*32
#define EDGE_D  32
#define MID_D   64
#define NC_IN   32
#define NC_OUT  32
#define M_IN    3
#define M_OUT   3
#define NFREQ   3
#define RDIM    96             // NC_IN * NFREQ
#define RAD_OUT 3072           // NC_OUT * RDIM

typedef unsigned long long u64;

// Scratch: h2 transposed [k][e] for coalesced GEMM loads, tmp[e][r][m]
__device__ float g_h2T[MID_D * E_TOT];          // 8 MB
__device__ float g_tmp[E_TOT * RDIM * M_OUT];   // 37.75 MB

__device__ __forceinline__ float warp_sum(float v) {
#pragma unroll
    for (int o = 16; o; o >>= 1) v += __shfl_xor_sync(0xffffffffu, v, o);
    return v;
}

__device__ __forceinline__ float gelu_exact(float x) {
    return 0.5f * x * (1.0f + erff(x * 0.70710678118654752f));
}

// packed fp32x2 FMA: d = a * b + d (per 32-bit half, exact fp32)
__device__ __forceinline__ void ffma2(u64& d, u64 a, u64 b) {
    asm("fma.rn.f32x2 %0, %1, %2, %0;" : "+l"(d) : "l"(a), "l"(b));
}
__device__ __forceinline__ u64 dup2(float w) {
    u64 r;
    asm("mov.b64 %0, {%1, %1};" : "=l"(r) : "f"(w));
    return r;
}
__device__ __forceinline__ float lo32(u64 v) {
    return __int_as_float((int)(unsigned)(v & 0xffffffffu));
}
__device__ __forceinline__ float hi32(u64 v) {
    return __int_as_float((int)(unsigned)(v >> 32));
}

// ---------------------------------------------------------------------------
// Kernel 1: radial MLP (layers 1-2) + per-edge feats@basis. (unchanged)
// One warp per edge; 8 edges per 256-thread block.
// ---------------------------------------------------------------------------
__global__ __launch_bounds__(256) void k_mlp(
    const float* __restrict__ edges, const float* __restrict__ feats,
    const float* __restrict__ basis,
    const float* __restrict__ W1, const float* __restrict__ b1,
    const float* __restrict__ g1, const float* __restrict__ be1,
    const float* __restrict__ W2, const float* __restrict__ b2,
    const float* __restrict__ g2, const float* __restrict__ be2)
{
    __shared__ float W1s[EDGE_D * MID_D];
    __shared__ float W2s[MID_D * MID_D];
    __shared__ float b1s[64], g1s[64], be1s[64], b2s[64], g2s[64], be2s[64];

    int tid = threadIdx.x;
    for (int i = tid; i < EDGE_D * MID_D; i += 256) W1s[i] = W1[i];
    for (int i = tid; i < MID_D * MID_D; i += 256) W2s[i] = W2[i];
    if (tid < 64) {
        b1s[tid] = b1[tid]; g1s[tid] = g1[tid]; be1s[tid] = be1[tid];
        b2s[tid] = b2[tid]; g2s[tid] = g2[tid]; be2s[tid] = be2[tid];
    }
    __syncthreads();

    int warp = tid >> 5, lane = tid & 31;
    int e = blockIdx.x * 8 + warp;

    float x = edges[e * EDGE_D + lane];
    float a0 = b1s[lane], a1 = b1s[lane + 32];
#pragma unroll
    for (int i = 0; i < 32; i++) {
        float xi = __shfl_sync(0xffffffffu, x, i);
        a0 = fmaf(xi, W1s[i * 64 + lane], a0);
        a1 = fmaf(xi, W1s[i * 64 + 32 + lane], a1);
    }
    float mean = warp_sum(a0 + a1) * (1.0f / 64.0f);
    float d0 = a0 - mean, d1 = a1 - mean;
    float var = warp_sum(d0 * d0 + d1 * d1) * (1.0f / 64.0f);
    float inv = rsqrtf(var + 1e-5f);
    a0 = gelu_exact(d0 * inv * g1s[lane] + be1s[lane]);
    a1 = gelu_exact(d1 * inv * g1s[lane + 32] + be1s[lane + 32]);

    float c0 = b2s[lane], c1 = b2s[lane + 32];
#pragma unroll
    for (int i = 0; i < 32; i++) {
        float xi = __shfl_sync(0xffffffffu, a0, i);
        c0 = fmaf(xi, W2s[i * 64 + lane], c0);
        c1 = fmaf(xi, W2s[i * 64 + 32 + lane], c1);
    }
#pragma unroll
    for (int i = 0; i < 32; i++) {
        float xi = __shfl_sync(0xffffffffu, a1, i);
        c0 = fmaf(xi, W2s[(i + 32) * 64 + lane], c0);
        c1 = fmaf(xi, W2s[(i + 32) * 64 + 32 + lane], c1);
    }
    mean = warp_sum(c0 + c1) * (1.0f / 64.0f);
    d0 = c0 - mean; d1 = c1 - mean;
    var = warp_sum(d0 * d0 + d1 * d1) * (1.0f / 64.0f);
    inv = rsqrtf(var + 1e-5f);
    c0 = gelu_exact(d0 * inv * g2s[lane] + be2s[lane]);
    c1 = gelu_exact(d1 * inv * g2s[lane + 32] + be2s[lane + 32]);

    g_h2T[lane * E_TOT + e] = c0;
    g_h2T[(lane + 32) * E_TOT + e] = c1;

    float f0 = feats[e * 96 + lane * 3 + 0];
    float f1 = feats[e * 96 + lane * 3 + 1];
    float f2 = feats[e * 96 + lane * 3 + 2];
    const float* bs = basis + e * 27;
    float* tp = g_tmp + (size_t)e * 288 + lane * 9;
#pragma unroll
    for (int c = 0; c < 9; c++)
        tp[c] = fmaf(f0, bs[c], fmaf(f1, bs[9 + c], f2 * bs[18 + c]));
}

// ---------------------------------------------------------------------------
// Kernel 2: fused h2 @ W3 -> rw in registers (f32x2, r-pairs packed from SMEM)
//           -> contract with tmp.
// CTA: 64 edges, 256 threads = 8 (tx: 12 r's, as 6 packed pairs) x 32 (ty: 2 edges).
// Thread tile: 2 edges x 6 r-pairs = 12 FFMA2 per k-step; only 2 MOV dups/k.
// K loop split in two 32-k passes; static SMEM = 28 KB -> 3 CTAs/SM.
// ---------------------------------------------------------------------------
__global__ __launch_bounds__(256, 3) void k_main(
    const float* __restrict__ W3, float* __restrict__ out)
{
    __shared__ float Hs[MID_D * 64];    // Hs[k*64 + e]            16 KB
    __shared__ float W3s[32 * 96];      // W3s[kk*96 + r] (half-K) 12 KB

    int tid = threadIdx.x;
    int e0 = blockIdx.x * 64;
    int tx = tid & 7;    // r-group: r = tx*12 .. tx*12+11 (6 packed pairs)
    int ty = tid >> 3;   // edges ty*2, ty*2+1

    // Load H tile (coalesced from transposed h2)
    {
        float4* Hs4 = (float4*)Hs;
        for (int i = tid; i < (MID_D * 64) / 4; i += 256) {
            int k = i >> 4, e4 = i & 15;
            Hs4[i] = *(const float4*)&g_h2T[k * E_TOT + e0 + e4 * 4];
        }
    }

    for (int o = 0; o < 32; ++o) {
        u64 acc[2][6];
#pragma unroll
        for (int p = 0; p < 2; p++)
#pragma unroll
            for (int r = 0; r < 6; r++) acc[p][r] = 0ull;

        for (int pass = 0; pass < 2; ++pass) {
            __syncthreads();   // protect W3s from previous readers (covers Hs @o=0)
            // Load half-K W3 slice: rows pass*32..+31, cols o*96..+95
            for (int i = tid; i < (32 * 96) / 4; i += 256) {
                int kk = i / 24, r4 = i % 24;
                ((float4*)W3s)[i] = *(const float4*)
                    &W3[(pass * 32 + kk) * RAD_OUT + o * 96 + r4 * 4];
            }
            __syncthreads();

#pragma unroll 8
            for (int kk = 0; kk < 32; kk++) {
                float2 hv = *(const float2*)&Hs[(pass * 32 + kk) * 64 + ty * 2];
                u64 ha = dup2(hv.x), hb = dup2(hv.y);
                const ulonglong2* wr = (const ulonglong2*)&W3s[kk * 96 + tx * 12];
                ulonglong2 wa = wr[0], wb = wr[1], wc = wr[2];
                ffma2(acc[0][0], ha, wa.x); ffma2(acc[0][1], ha, wa.y);
                ffma2(acc[0][2], ha, wb.x); ffma2(acc[0][3], ha, wb.y);
                ffma2(acc[0][4], ha, wc.x); ffma2(acc[0][5], ha, wc.y);
                ffma2(acc[1][0], hb, wa.x); ffma2(acc[1][1], hb, wa.y);
                ffma2(acc[1][2], hb, wb.x); ffma2(acc[1][3], hb, wb.y);
                ffma2(acc[1][4], hb, wc.x); ffma2(acc[1][5], hb, wc.y);
            }
        }

        // Epilogue: out[e, o, m] = sum_r rw[e, r] * tmp[e, r, m]
        // acc[p][rp] holds (r=2rp, r=2rp+1) for edge ty*2+p. Butterfly over tx=8.
#pragma unroll
        for (int p = 0; p < 2; p++) {
            int e = ty * 2 + p;
            const float4* tp = (const float4*)
                (g_tmp + (size_t)(e0 + e) * 288 + tx * 36);
            float s0 = 0.f, s1 = 0.f, s2 = 0.f;
#pragma unroll
            for (int c = 0; c < 3; c++) {   // r = 4c .. 4c+3
                float4 t0 = tp[c * 3 + 0];
                float4 t1 = tp[c * 3 + 1];
                float4 t2 = tp[c * 3 + 2];
                float cv0 = lo32(acc[p][c * 2 + 0]);
                float cv1 = hi32(acc[p][c * 2 + 0]);
                float cv2 = lo32(acc[p][c * 2 + 1]);
                float cv3 = hi32(acc[p][c * 2 + 1]);
                s0 = fmaf(cv0, t0.x, s0); s1 = fmaf(cv0, t0.y, s1); s2 = fmaf(cv0, t0.z, s2);
                s0 = fmaf(cv1, t0.w, s0); s1 = fmaf(cv1, t1.x, s1); s2 = fmaf(cv1, t1.y, s2);
                s0 = fmaf(cv2, t1.z, s0); s1 = fmaf(cv2, t1.w, s1); s2 = fmaf(cv2, t2.x, s2);
                s0 = fmaf(cv3, t2.y, s0); s1 = fmaf(cv3, t2.z, s1); s2 = fmaf(cv3, t2.w, s2);
            }
#pragma unroll
            for (int m = 4; m; m >>= 1) {
                s0 += __shfl_xor_sync(0xffffffffu, s0, m);
                s1 += __shfl_xor_sync(0xffffffffu, s1, m);
                s2 += __shfl_xor_sync(0xffffffffu, s2, m);
            }
            if (tx == 0) {
                float* op = out + (size_t)(e0 + e) * 96 + o * 3;
                op[0] = s0; op[1] = s1; op[2] = s2;
            }
        }
    }
}

// ---------------------------------------------------------------------------
extern "C" void kernel_launch(void* const* d_in, const int* in_sizes, int n_in,
                              void* d_out, int out_size)
{
    const float* edges = (const float*)d_in[0];
    const float* feats = (const float*)d_in[1];
    const float* basis = (const float*)d_in[2];
    const float* W1    = (const float*)d_in[3];
    const float* b1    = (const float*)d_in[4];
    const float* g1    = (const float*)d_in[5];
    const float* be1   = (const float*)d_in[6];
    const float* W2    = (const float*)d_in[7];
    const float* b2    = (const float*)d_in[8];
    const float* g2    = (const float*)d_in[9];
    const float* be2   = (const float*)d_in[10];
    const float* W3    = (const float*)d_in[11];
    float* out = (float*)d_out;

    // Host-side attribute set (not a stream op; capture-safe, no allocation).
    // Max carveout so 3 CTAs x 28 KB of k_main can co-reside.
    cudaFuncSetAttribute(k_main,
                         cudaFuncAttributePreferredSharedMemoryCarveout, 100);

    k_mlp<<<E_TOT / 8, 256>>>(edges, feats, basis, W1, b1, g1, be1,
                              W2, b2, g2, be2);
    k_main<<<E_TOT / 64, 256>>>(W3, out);
}

// round 12
// speedup vs baseline: 2.6970x; 2.6970x over previous
#include <cuda_runtime.h>
#include <math.h>
#include <stdint.h>

// Problem constants (fixed by setup_inputs)
#define E_TOT   32768          // B*N*K = 1*1024*32
#define EDGE_D  32
#define MID_D   64
#define NC_IN   32
#define NC_OUT  32
#define RDIM    96             // NC_IN * NFREQ
#define RAD_OUT 3072           // NC_OUT * RDIM

// Scratch
__device__ float g_h2[E_TOT * MID_D];           // h2[e][k], tf32-rounded, 8 MB
__device__ float g_W3T[RAD_OUT * MID_D];        // B rows: [rb][rloc*32+o][k], 3 MB
__device__ float g_tmp[E_TOT * RDIM * 3];       // tmp[e][r][m], 37.75 MB

__device__ __forceinline__ float warp_sum(float v) {
#pragma unroll
    for (int o = 16; o; o >>= 1) v += __shfl_xor_sync(0xffffffffu, v, o);
    return v;
}
__device__ __forceinline__ float gelu_exact(float x) {
    return 0.5f * x * (1.0f + erff(x * 0.70710678118654752f));
}
__device__ __forceinline__ float tf32_rna(float x) {
    uint32_t u;
    asm("cvt.rna.tf32.f32 %0, %1;" : "=r"(u) : "f"(x));
    return __uint_as_float(u);
}

// warp-level tf32 MMA (sm_80+ PTX; legal on compute_103 non-'a' target)
__device__ __forceinline__ void mma_tf32(
    float& d0, float& d1, float& d2, float& d3,
    uint32_t a0, uint32_t a1, uint32_t a2, uint32_t a3,
    uint32_t b0, uint32_t b1)
{
    asm volatile(
        "mma.sync.aligned.m16n8k8.row.col.f32.tf32.tf32.f32 "
        "{%0,%1,%2,%3}, {%4,%5,%6,%7}, {%8,%9}, {%0,%1,%2,%3};"
        : "+f"(d0), "+f"(d1), "+f"(d2), "+f"(d3)
        : "r"(a0), "r"(a1), "r"(a2), "r"(a3), "r"(b0), "r"(b1));
}

// ---------------------------------------------------------------------------
// Kernel 0: transpose + tf32-round W3 into B-row order n = rb*96 + rloc*32 + o
//           (r = rb*3 + rloc). g_W3T[n*64 + k] = rna(W3[k*3072 + o*96 + r]).
// ---------------------------------------------------------------------------
__global__ __launch_bounds__(256) void k_w3t(const float* __restrict__ W3) {
    int idx = blockIdx.x * 256 + threadIdx.x;     // 0 .. 3072*64-1
    int k = idx & 63, n = idx >> 6;
    int rb = n / 96, t = n - rb * 96;
    int rloc = t >> 5, o = t & 31;
    g_W3T[idx] = tf32_rna(W3[k * RAD_OUT + o * 96 + rb * 3 + rloc]);
}

// ---------------------------------------------------------------------------
// Kernel 1: radial MLP (layers 1-2) + per-edge feats@basis.
// One warp per edge; 8 edges per 256-thread block. h2 row-major, tf32-rounded.
// ---------------------------------------------------------------------------
__global__ __launch_bounds__(256) void k_mlp(
    const float* __restrict__ edges, const float* __restrict__ feats,
    const float* __restrict__ basis,
    const float* __restrict__ W1, const float* __restrict__ b1,
    const float* __restrict__ g1, const float* __restrict__ be1,
    const float* __restrict__ W2, const float* __restrict__ b2,
    const float* __restrict__ g2, const float* __restrict__ be2)
{
    __shared__ float W1s[EDGE_D * MID_D];
    __shared__ float W2s[MID_D * MID_D];
    __shared__ float b1s[64], g1s[64], be1s[64], b2s[64], g2s[64], be2s[64];

    int tid = threadIdx.x;
    for (int i = tid; i < EDGE_D * MID_D; i += 256) W1s[i] = W1[i];
    for (int i = tid; i < MID_D * MID_D; i += 256) W2s[i] = W2[i];
    if (tid < 64) {
        b1s[tid] = b1[tid]; g1s[tid] = g1[tid]; be1s[tid] = be1[tid];
        b2s[tid] = b2[tid]; g2s[tid] = g2[tid]; be2s[tid] = be2[tid];
    }
    __syncthreads();

    int warp = tid >> 5, lane = tid & 31;
    int e = blockIdx.x * 8 + warp;

    float x = edges[e * EDGE_D + lane];
    float a0 = b1s[lane], a1 = b1s[lane + 32];
#pragma unroll
    for (int i = 0; i < 32; i++) {
        float xi = __shfl_sync(0xffffffffu, x, i);
        a0 = fmaf(xi, W1s[i * 64 + lane], a0);
        a1 = fmaf(xi, W1s[i * 64 + 32 + lane], a1);
    }
    float mean = warp_sum(a0 + a1) * (1.0f / 64.0f);
    float d0 = a0 - mean, d1 = a1 - mean;
    float var = warp_sum(d0 * d0 + d1 * d1) * (1.0f / 64.0f);
    float inv = rsqrtf(var + 1e-5f);
    a0 = gelu_exact(d0 * inv * g1s[lane] + be1s[lane]);
    a1 = gelu_exact(d1 * inv * g1s[lane + 32] + be1s[lane + 32]);

    float c0 = b2s[lane], c1 = b2s[lane + 32];
#pragma unroll
    for (int i = 0; i < 32; i++) {
        float xi = __shfl_sync(0xffffffffu, a0, i);
        c0 = fmaf(xi, W2s[i * 64 + lane], c0);
        c1 = fmaf(xi, W2s[i * 64 + 32 + lane], c1);
    }
#pragma unroll
    for (int i = 0; i < 32; i++) {
        float xi = __shfl_sync(0xffffffffu, a1, i);
        c0 = fmaf(xi, W2s[(i + 32) * 64 + lane], c0);
        c1 = fmaf(xi, W2s[(i + 32) * 64 + 32 + lane], c1);
    }
    mean = warp_sum(c0 + c1) * (1.0f / 64.0f);
    d0 = c0 - mean; d1 = c1 - mean;
    var = warp_sum(d0 * d0 + d1 * d1) * (1.0f / 64.0f);
    inv = rsqrtf(var + 1e-5f);
    c0 = gelu_exact(d0 * inv * g2s[lane] + be2s[lane]);
    c1 = gelu_exact(d1 * inv * g2s[lane + 32] + be2s[lane + 32]);

    g_h2[e * MID_D + lane]      = tf32_rna(c0);
    g_h2[e * MID_D + 32 + lane] = tf32_rna(c1);

    float f0 = feats[e * 96 + lane * 3 + 0];
    float f1 = feats[e * 96 + lane * 3 + 1];
    float f2 = feats[e * 96 + lane * 3 + 2];
    const float* bs = basis + e * 27;
    float* tp = g_tmp + (size_t)e * 288 + lane * 9;
#pragma unroll
    for (int c = 0; c < 9; c++)
        tp[c] = fmaf(f0, bs[c], fmaf(f1, bs[9 + c], f2 * bs[18 + c]));
}

// ---------------------------------------------------------------------------
// Kernel 2: warp-level tf32 mma.sync GEMM + fused contraction.
// CTA = 128 edges, 256 threads = 8 warps x 16 edges.
// Per rb (32 blocks of 3 r's): D(16x96 per warp) = A(16x64) @ B_rb(96x64)^T
// via 12 n-tiles x 8 k-steps of m16n8k8. A fragments persist in registers
// across all rb. D folds into 48 per-thread accumulators (2e x 8o x 3m)
// using 9 tmp floats/edge; each (e,o,m) owned by exactly one thread ->
// no reduction, contiguous stores.
// ---------------------------------------------------------------------------
__global__ __launch_bounds__(256) void k_main(float* __restrict__ out)
{
    __shared__ float Bs[96 * 68];   // padded stride 68 floats -> conflict-free frags

    int tid = threadIdx.x, w = tid >> 5, lane = tid & 31;
    int g = lane >> 2, q = lane & 3;
    int e0 = blockIdx.x * 128;
    int ew = e0 + w * 16;

    // A fragments: a[ks][0..3] per m16n8k8 row.col layout; reused for all rb
    uint32_t a[8][4];
    {
        const float* A0 = g_h2 + (size_t)(ew + g) * MID_D;
        const float* A1 = g_h2 + (size_t)(ew + g + 8) * MID_D;
#pragma unroll
        for (int ks = 0; ks < 8; ks++) {
            a[ks][0] = __float_as_uint(A0[ks * 8 + q]);
            a[ks][1] = __float_as_uint(A1[ks * 8 + q]);
            a[ks][2] = __float_as_uint(A0[ks * 8 + q + 4]);
            a[ks][3] = __float_as_uint(A1[ks * 8 + q + 4]);
        }
    }

    float acc[2][8][3];
#pragma unroll
    for (int s = 0; s < 2; s++)
#pragma unroll
        for (int i = 0; i < 8; i++)
#pragma unroll
            for (int m = 0; m < 3; m++) acc[s][i][m] = 0.0f;

    const float* tA = g_tmp + (size_t)(ew + g) * 288;
    const float* tB = g_tmp + (size_t)(ew + g + 8) * 288;

    for (int rb = 0; rb < 32; rb++) {
        __syncthreads();   // previous rb's Bs consumers done
        // Stage B_rb: 96 rows x 64 k -> Bs[row*68 + k], coalesced float4
        const float* src = g_W3T + rb * 96 * 64;
        for (int i = tid; i < 96 * 16; i += 256) {
            int row = i >> 4, k4 = i & 15;
            *(float4*)&Bs[row * 68 + k4 * 4] = *(const float4*)&src[row * 64 + k4 * 4];
        }
        __syncthreads();

        float t9A[9], t9B[9];
#pragma unroll
        for (int j = 0; j < 9; j++) {
            t9A[j] = __ldg(&tA[rb * 9 + j]);
            t9B[j] = __ldg(&tB[rb * 9 + j]);
        }

#pragma unroll
        for (int j = 0; j < 12; j++) {           // n-tile: cols j*8..j*8+7
            float d0 = 0.f, d1 = 0.f, d2 = 0.f, d3 = 0.f;
            const float* bp = &Bs[(j * 8 + g) * 68 + q];   // B[n][k] frag base
#pragma unroll
            for (int ks = 0; ks < 8; ks++) {
                uint32_t b0 = __float_as_uint(bp[ks * 8]);
                uint32_t b1 = __float_as_uint(bp[ks * 8 + 4]);
                mma_tf32(d0, d1, d2, d3,
                         a[ks][0], a[ks][1], a[ks][2], a[ks][3], b0, b1);
            }
            // D cols n0 = j*8+2q, n0+1; rloc = j>>2, o-slot = (j&3)*2 {+1}
            int rl = j >> 2, jm = j & 3;
#pragma unroll
            for (int m = 0; m < 3; m++) {
                float ta = t9A[rl * 3 + m], tb = t9B[rl * 3 + m];
                acc[0][jm * 2 + 0][m] = fmaf(d0, ta, acc[0][jm * 2 + 0][m]);
                acc[0][jm * 2 + 1][m] = fmaf(d1, ta, acc[0][jm * 2 + 1][m]);
                acc[1][jm * 2 + 0][m] = fmaf(d2, tb, acc[1][jm * 2 + 0][m]);
                acc[1][jm * 2 + 1][m] = fmaf(d3, tb, acc[1][jm * 2 + 1][m]);
            }
        }
    }

    // Store: edge s half, o = jm*8 + 2q (+1), 6 contiguous floats each
#pragma unroll
    for (int s = 0; s < 2; s++) {
        float* op = out + (size_t)(ew + g + s * 8) * 96;
#pragma unroll
        for (int jm = 0; jm < 4; jm++) {
            float* p = op + (jm * 8 + 2 * q) * 3;
            float2* p2 = (float2*)p;
            p2[0] = make_float2(acc[s][jm * 2][0],     acc[s][jm * 2][1]);
            p2[1] = make_float2(acc[s][jm * 2][2],     acc[s][jm * 2 + 1][0]);
            p2[2] = make_float2(acc[s][jm * 2 + 1][1], acc[s][jm * 2 + 1][2]);
        }
    }
}

// ---------------------------------------------------------------------------
extern "C" void kernel_launch(void* const* d_in, const int* in_sizes, int n_in,
                              void* d_out, int out_size)
{
    const float* edges = (const float*)d_in[0];
    const float* feats = (const float*)d_in[1];
    const float* basis = (const float*)d_in[2];
    const float* W1    = (const float*)d_in[3];
    const float* b1    = (const float*)d_in[4];
    const float* g1    = (const float*)d_in[5];
    const float* be1   = (const float*)d_in[6];
    const float* W2    = (const float*)d_in[7];
    const float* b2    = (const float*)d_in[8];
    const float* g2    = (const float*)d_in[9];
    const float* be2   = (const float*)d_in[10];
    const float* W3    = (const float*)d_in[11];
    float* out = (float*)d_out;

    k_w3t<<<(RAD_OUT * MID_D) / 256, 256>>>(W3);
    k_mlp<<<E_TOT / 8, 256>>>(edges, feats, basis, W1, b1, g1, be1,
                              W2, b2, g2, be2);
    k_main<<<E_TOT / 128, 256>>>(out);
}

// round 14
// speedup vs baseline: 3.0815x; 1.1426x over previous
#include <cuda_runtime.h>
#include <math.h>
#include <stdint.h>

// Problem constants (fixed by setup_inputs)
#define E_TOT   32768          // B*N*K = 1*1024*32
#define EDGE_D  32
#define MID_D   64
#define RAD_OUT 3072           // NC_OUT * RDIM

// Scratch
__device__ float g_h2[E_TOT * MID_D];        // h2[e][k], tf32-rounded, 8 MB
__device__ float g_W3T[RAD_OUT * MID_D];     // fragment order [rb][j][lane][16], 3 MB
__device__ float g_tmp[E_TOT * 32 * 12];     // tmp[e][rb][12] (9 used + 3 pad), 50 MB

#define BSTRIDE  20                          // floats per lane chunk (80 B)
#define BBUF     (12 * 32 * BSTRIDE)         // 7680 floats per stage

__device__ __forceinline__ float warp_sum(float v) {
#pragma unroll
    for (int o = 16; o; o >>= 1) v += __shfl_xor_sync(0xffffffffu, v, o);
    return v;
}
__device__ __forceinline__ float gelu_exact(float x) {
    return 0.5f * x * (1.0f + erff(x * 0.70710678118654752f));
}
__device__ __forceinline__ float tf32_rna(float x) {
    uint32_t u;
    asm("cvt.rna.tf32.f32 %0, %1;" : "=r"(u) : "f"(x));
    return __uint_as_float(u);
}
__device__ __forceinline__ uint32_t smem_u32(const void* p) {
    uint32_t a;
    asm("{ .reg .u64 t; cvta.to.shared.u64 t, %1; cvt.u32.u64 %0, t; }"
        : "=r"(a) : "l"(p));
    return a;
}
__device__ __forceinline__ void cp16(uint32_t daddr, const float* src) {
    asm volatile("cp.async.cg.shared.global [%0], [%1], 16;"
                 :: "r"(daddr), "l"(src));
}
__device__ __forceinline__ void mma_tf32(
    float& d0, float& d1, float& d2, float& d3,
    uint32_t a0, uint32_t a1, uint32_t a2, uint32_t a3,
    uint32_t b0, uint32_t b1)
{
    asm volatile(
        "mma.sync.aligned.m16n8k8.row.col.f32.tf32.tf32.f32 "
        "{%0,%1,%2,%3}, {%4,%5,%6,%7}, {%8,%9}, {%0,%1,%2,%3};"
        : "+f"(d0), "+f"(d1), "+f"(d2), "+f"(d3)
        : "r"(a0), "r"(a1), "r"(a2), "r"(a3), "r"(b0), "r"(b1));
}

// ---------------------------------------------------------------------------
// Kernel 0: W3 -> fragment-ordered tf32 W3T.
// element idx = ((rb*12 + j)*32 + lane)*16 + (ks*2 + half)
//   holds B[n=j*8+g][k=ks*8+q+half*4] for n = rloc*32+o, r = rb*3+rloc.
// ---------------------------------------------------------------------------
__global__ __launch_bounds__(256) void k_w3t(const float* __restrict__ W3) {
    int e = blockIdx.x * 256 + threadIdx.x;       // 0 .. 196607
    int pos  = e & 15;
    int lane = (e >> 4) & 31;
    int t    = e >> 9;                            // rb*12 + j
    int j = t % 12, rb = t / 12;
    int g = lane >> 2, q = lane & 3;
    int ks = pos >> 1, half = pos & 1;
    int n = j * 8 + g;
    int rloc = n >> 5, o = n & 31;
    int k = ks * 8 + q + half * 4;
    g_W3T[e] = tf32_rna(W3[k * RAD_OUT + o * 96 + rb * 3 + rloc]);
}

// ---------------------------------------------------------------------------
// Kernel 1: radial MLP (layers 1-2) + per-edge feats@basis.
// One warp per TWO edges (2x ILP, CSE'd weight LDS); 16 edges / 256-thr block.
// ---------------------------------------------------------------------------
__global__ __launch_bounds__(256) void k_mlp(
    const float* __restrict__ edges, const float* __restrict__ feats,
    const float* __restrict__ basis,
    const float* __restrict__ W1, const float* __restrict__ b1,
    const float* __restrict__ g1, const float* __restrict__ be1,
    const float* __restrict__ W2, const float* __restrict__ b2,
    const float* __restrict__ g2, const float* __restrict__ be2)
{
    __shared__ float W1s[EDGE_D * MID_D];
    __shared__ float W2s[MID_D * MID_D];
    __shared__ float b1s[64], g1s[64], be1s[64], b2s[64], g2s[64], be2s[64];

    int tid = threadIdx.x;
    for (int i = tid; i < EDGE_D * MID_D; i += 256) W1s[i] = W1[i];
    for (int i = tid; i < MID_D * MID_D; i += 256) W2s[i] = W2[i];
    if (tid < 64) {
        b1s[tid] = b1[tid]; g1s[tid] = g1[tid]; be1s[tid] = be1[tid];
        b2s[tid] = b2[tid]; g2s[tid] = g2[tid]; be2s[tid] = be2[tid];
    }
    __syncthreads();

    int warp = tid >> 5, lane = tid & 31;
    int eA = blockIdx.x * 16 + warp * 2, eB = eA + 1;

    float xA = edges[eA * EDGE_D + lane];
    float xB = edges[eB * EDGE_D + lane];
    float a0A = b1s[lane], a1A = b1s[lane + 32];
    float a0B = a0A, a1B = a1A;
#pragma unroll
    for (int i = 0; i < 32; i++) {
        float wlo = W1s[i * 64 + lane], whi = W1s[i * 64 + 32 + lane];
        float xiA = __shfl_sync(0xffffffffu, xA, i);
        float xiB = __shfl_sync(0xffffffffu, xB, i);
        a0A = fmaf(xiA, wlo, a0A); a1A = fmaf(xiA, whi, a1A);
        a0B = fmaf(xiB, wlo, a0B); a1B = fmaf(xiB, whi, a1B);
    }
    // LN + GELU, edge A and B (independent chains)
    {
        float mA = warp_sum(a0A + a1A) * (1.0f / 64.0f);
        float mB = warp_sum(a0B + a1B) * (1.0f / 64.0f);
        float d0A = a0A - mA, d1A = a1A - mA;
        float d0B = a0B - mB, d1B = a1B - mB;
        float vA = warp_sum(d0A * d0A + d1A * d1A) * (1.0f / 64.0f);
        float vB = warp_sum(d0B * d0B + d1B * d1B) * (1.0f / 64.0f);
        float iA = rsqrtf(vA + 1e-5f), iB = rsqrtf(vB + 1e-5f);
        a0A = gelu_exact(d0A * iA * g1s[lane]      + be1s[lane]);
        a1A = gelu_exact(d1A * iA * g1s[lane + 32] + be1s[lane + 32]);
        a0B = gelu_exact(d0B * iB * g1s[lane]      + be1s[lane]);
        a1B = gelu_exact(d1B * iB * g1s[lane + 32] + be1s[lane + 32]);
    }

    float c0A = b2s[lane], c1A = b2s[lane + 32];
    float c0B = c0A, c1B = c1A;
#pragma unroll
    for (int i = 0; i < 32; i++) {
        float wlo = W2s[i * 64 + lane], whi = W2s[i * 64 + 32 + lane];
        float xiA = __shfl_sync(0xffffffffu, a0A, i);
        float xiB = __shfl_sync(0xffffffffu, a0B, i);
        c0A = fmaf(xiA, wlo, c0A); c1A = fmaf(xiA, whi, c1A);
        c0B = fmaf(xiB, wlo, c0B); c1B = fmaf(xiB, whi, c1B);
    }
#pragma unroll
    for (int i = 0; i < 32; i++) {
        float wlo = W2s[(i + 32) * 64 + lane], whi = W2s[(i + 32) * 64 + 32 + lane];
        float xiA = __shfl_sync(0xffffffffu, a1A, i);
        float xiB = __shfl_sync(0xffffffffu, a1B, i);
        c0A = fmaf(xiA, wlo, c0A); c1A = fmaf(xiA, whi, c1A);
        c0B = fmaf(xiB, wlo, c0B); c1B = fmaf(xiB, whi, c1B);
    }
    {
        float mA = warp_sum(c0A + c1A) * (1.0f / 64.0f);
        float mB = warp_sum(c0B + c1B) * (1.0f / 64.0f);
        float d0A = c0A - mA, d1A = c1A - mA;
        float d0B = c0B - mB, d1B = c1B - mB;
        float vA = warp_sum(d0A * d0A + d1A * d1A) * (1.0f / 64.0f);
        float vB = warp_sum(d0B * d0B + d1B * d1B) * (1.0f / 64.0f);
        float iA = rsqrtf(vA + 1e-5f), iB = rsqrtf(vB + 1e-5f);
        c0A = gelu_exact(d0A * iA * g2s[lane]      + be2s[lane]);
        c1A = gelu_exact(d1A * iA * g2s[lane + 32] + be2s[lane + 32]);
        c0B = gelu_exact(d0B * iB * g2s[lane]      + be2s[lane]);
        c1B = gelu_exact(d1B * iB * g2s[lane + 32] + be2s[lane + 32]);
    }

    g_h2[eA * MID_D + lane]      = tf32_rna(c0A);
    g_h2[eA * MID_D + 32 + lane] = tf32_rna(c1A);
    g_h2[eB * MID_D + lane]      = tf32_rna(c0B);
    g_h2[eB * MID_D + 32 + lane] = tf32_rna(c1B);

    // tmp[e][rb=lane][rloc*3+m] (+3 pad), rloc = f since r = lane*3+f
#pragma unroll
    for (int s = 0; s < 2; s++) {
        int e = s ? eB : eA;
        float f0 = feats[e * 96 + lane * 3 + 0];
        float f1 = feats[e * 96 + lane * 3 + 1];
        float f2 = feats[e * 96 + lane * 3 + 2];
        const float* bs = basis + e * 27;
        float v[12];
#pragma unroll
        for (int c = 0; c < 9; c++)
            v[c] = fmaf(f0, bs[c], fmaf(f1, bs[9 + c], f2 * bs[18 + c]));
        v[9] = v[10] = v[11] = 0.0f;
        float4* tp = (float4*)(g_tmp + (size_t)e * 384 + lane * 12);
        tp[0] = make_float4(v[0], v[1], v[2], v[3]);
        tp[1] = make_float4(v[4], v[5], v[6], v[7]);
        tp[2] = make_float4(v[8], v[9], v[10], v[11]);
    }
}

// ---------------------------------------------------------------------------
// Kernel 2: tf32 mma.sync GEMM + fused contraction, cp.async double-buffered B.
// CTA = 128 edges, 256 threads = 8 warps x 16 edges; 2 CTAs/SM.
// Per rb: D(16x96/warp) = A(16x64) @ B_rb(96x64)^T via 12 n-tiles of m16n8k8;
// fold into 48 persistent per-thread accumulators with 9 tmp floats/edge.
// ---------------------------------------------------------------------------
__global__ void __launch_bounds__(256, 2) k_main(float* __restrict__ out)
{
    extern __shared__ float Bs[];   // 2 * BBUF floats (61440 B)
    int tid = threadIdx.x, w = tid >> 5, lane = tid & 31;
    int g = lane >> 2, q = lane & 3;
    int e0 = blockIdx.x * 128, ew = e0 + w * 16;
    uint32_t sb = smem_u32(Bs);

    // prologue: prefetch rb=0 into stage 0
#pragma unroll
    for (int i = 0; i < 6; i++) {
        int c = tid + 256 * i;
        int j = c >> 7, ln = (c >> 2) & 31, cc = c & 3;
        cp16(sb + ((j * 32 + ln) * BSTRIDE + cc * 4) * 4, g_W3T + c * 4);
    }
    asm volatile("cp.async.commit_group;" ::: "memory");

    // A fragments (persist across all rb)
    uint32_t a[8][4];
    {
        const float* A0 = g_h2 + (size_t)(ew + g) * MID_D;
        const float* A1 = A0 + 8 * MID_D;
#pragma unroll
        for (int ks = 0; ks < 8; ks++) {
            a[ks][0] = __float_as_uint(A0[ks * 8 + q]);
            a[ks][1] = __float_as_uint(A1[ks * 8 + q]);
            a[ks][2] = __float_as_uint(A0[ks * 8 + q + 4]);
            a[ks][3] = __float_as_uint(A1[ks * 8 + q + 4]);
        }
    }

    float acc[2][8][3];
#pragma unroll
    for (int s = 0; s < 2; s++)
#pragma unroll
        for (int i = 0; i < 8; i++)
#pragma unroll
            for (int m = 0; m < 3; m++) acc[s][i][m] = 0.0f;

    const float4* tAp = (const float4*)(g_tmp + (size_t)(ew + g) * 384);
    const float4* tBp = (const float4*)(g_tmp + (size_t)(ew + g + 8) * 384);

    for (int rb = 0; rb < 32; rb++) {
        asm volatile("cp.async.wait_group 0;" ::: "memory");
        __syncthreads();                 // stage rb visible; all done with other buf
        if (rb < 31) {
            const float* src = g_W3T + (rb + 1) * 6144;
            uint32_t dbase = sb + ((rb + 1) & 1) * (BBUF * 4);
#pragma unroll
            for (int i = 0; i < 6; i++) {
                int c = tid + 256 * i;
                int j = c >> 7, ln = (c >> 2) & 31, cc = c & 3;
                cp16(dbase + ((j * 32 + ln) * BSTRIDE + cc * 4) * 4, src + c * 4);
            }
            asm volatile("cp.async.commit_group;" ::: "memory");
        }

        float4 ta0 = tAp[rb * 3], ta1 = tAp[rb * 3 + 1], ta2 = tAp[rb * 3 + 2];
        float4 tb0 = tBp[rb * 3], tb1 = tBp[rb * 3 + 1], tb2 = tBp[rb * 3 + 2];
        float t9A[9] = {ta0.x, ta0.y, ta0.z, ta0.w, ta1.x, ta1.y, ta1.z, ta1.w, ta2.x};
        float t9B[9] = {tb0.x, tb0.y, tb0.z, tb0.w, tb1.x, tb1.y, tb1.z, tb1.w, tb2.x};

        const float* bbase = Bs + (rb & 1) * BBUF;
#pragma unroll
        for (int j = 0; j < 12; j++) {
            const float4* bp = (const float4*)(bbase + (j * 32 + lane) * BSTRIDE);
            float4 f0 = bp[0], f1 = bp[1], f2 = bp[2], f3 = bp[3];
            float d0 = 0.f, d1 = 0.f, d2 = 0.f, d3 = 0.f;
            float u0 = 0.f, u1 = 0.f, u2 = 0.f, u3 = 0.f;
            mma_tf32(d0, d1, d2, d3, a[0][0], a[0][1], a[0][2], a[0][3],
                     __float_as_uint(f0.x), __float_as_uint(f0.y));
            mma_tf32(u0, u1, u2, u3, a[1][0], a[1][1], a[1][2], a[1][3],
                     __float_as_uint(f0.z), __float_as_uint(f0.w));
            mma_tf32(d0, d1, d2, d3, a[2][0], a[2][1], a[2][2], a[2][3],
                     __float_as_uint(f1.x), __float_as_uint(f1.y));
            mma_tf32(u0, u1, u2, u3, a[3][0], a[3][1], a[3][2], a[3][3],
                     __float_as_uint(f1.z), __float_as_uint(f1.w));
            mma_tf32(d0, d1, d2, d3, a[4][0], a[4][1], a[4][2], a[4][3],
                     __float_as_uint(f2.x), __float_as_uint(f2.y));
            mma_tf32(u0, u1, u2, u3, a[5][0], a[5][1], a[5][2], a[5][3],
                     __float_as_uint(f2.z), __float_as_uint(f2.w));
            mma_tf32(d0, d1, d2, d3, a[6][0], a[6][1], a[6][2], a[6][3],
                     __float_as_uint(f3.x), __float_as_uint(f3.y));
            mma_tf32(u0, u1, u2, u3, a[7][0], a[7][1], a[7][2], a[7][3],
                     __float_as_uint(f3.z), __float_as_uint(f3.w));
            d0 += u0; d1 += u1; d2 += u2; d3 += u3;

            int rl = j >> 2, jm = j & 3;
#pragma unroll
            for (int m = 0; m < 3; m++) {
                float ta = t9A[rl * 3 + m], tb = t9B[rl * 3 + m];
                acc[0][jm * 2 + 0][m] = fmaf(d0, ta, acc[0][jm * 2 + 0][m]);
                acc[0][jm * 2 + 1][m] = fmaf(d1, ta, acc[0][jm * 2 + 1][m]);
                acc[1][jm * 2 + 0][m] = fmaf(d2, tb, acc[1][jm * 2 + 0][m]);
                acc[1][jm * 2 + 1][m] = fmaf(d3, tb, acc[1][jm * 2 + 1][m]);
            }
        }
    }

    // Store: edge half s, o = jm*8 + 2q (+1), 6 contiguous floats each
#pragma unroll
    for (int s = 0; s < 2; s++) {
        float* op = out + (size_t)(ew + g + s * 8) * 96;
#pragma unroll
        for (int jm = 0; jm < 4; jm++) {
            float* p = op + (jm * 8 + 2 * q) * 3;
            float2* p2 = (float2*)p;
            p2[0] = make_float2(acc[s][jm * 2][0],     acc[s][jm * 2][1]);
            p2[1] = make_float2(acc[s][jm * 2][2],     acc[s][jm * 2 + 1][0]);
            p2[2] = make_float2(acc[s][jm * 2 + 1][1], acc[s][jm * 2 + 1][2]);
        }
    }
}

// ---------------------------------------------------------------------------
extern "C" void kernel_launch(void* const* d_in, const int* in_sizes, int n_in,
                              void* d_out, int out_size)
{
    const float* edges = (const float*)d_in[0];
    const float* feats = (const float*)d_in[1];
    const float* basis = (const float*)d_in[2];
    const float* W1    = (const float*)d_in[3];
    const float* b1    = (const float*)d_in[4];
    const float* g1    = (const float*)d_in[5];
    const float* be1   = (const float*)d_in[6];
    const float* W2    = (const float*)d_in[7];
    const float* b2    = (const float*)d_in[8];
    const float* g2    = (const float*)d_in[9];
    const float* be2   = (const float*)d_in[10];
    const float* W3    = (const float*)d_in[11];
    float* out = (float*)d_out;

    // Host-side attributes (not stream ops; capture-safe, no allocation)
    cudaFuncSetAttribute(k_main, cudaFuncAttributeMaxDynamicSharedMemorySize,
                         2 * BBUF * 4);
    cudaFuncSetAttribute(k_main,
                         cudaFuncAttributePreferredSharedMemoryCarveout, 100);

    k_w3t<<<(RAD_OUT * MID_D) / 256, 256>>>(W3);
    k_mlp<<<E_TOT / 16, 256>>>(edges, feats, basis, W1, b1, g1, be1,
                               W2, b2, g2, be2);
    k_main<<<E_TOT / 128, 256, 2 * BBUF * 4>>>(out);
}

// round 15
// speedup vs baseline: 4.7701x; 1.5480x over previous
#include <cuda_runtime.h>
#include <math.h>
#include <stdint.h>

// Problem constants (fixed by setup_inputs)
#define E_TOT   32768          // B*N*K = 1*1024*32
#define EDGE_D  32
#define MID_D   64
#define RAD_OUT 3072           // NC_OUT * RDIM

// Scratch
__device__ float g_h2[E_TOT * MID_D];        // h2[e][k], tf32-rounded, 8 MB
__device__ float g_W3T[RAD_OUT * MID_D];     // fragment order [rb][j][lane][16], 3 MB
__device__ float g_tmp[E_TOT * 32 * 12];     // tmp[e][rb][rl*4+m] (3 rl * 4), 50 MB

#define BSTRIDE  20                          // floats per lane chunk (80 B)
#define BBUF     (12 * 32 * BSTRIDE)         // 7680 floats per stage

__device__ __forceinline__ float warp_sum(float v) {
#pragma unroll
    for (int o = 16; o; o >>= 1) v += __shfl_xor_sync(0xffffffffu, v, o);
    return v;
}
__device__ __forceinline__ float gelu_exact(float x) {
    return 0.5f * x * (1.0f + erff(x * 0.70710678118654752f));
}
__device__ __forceinline__ float tf32_rna(float x) {
    uint32_t u;
    asm("cvt.rna.tf32.f32 %0, %1;" : "=r"(u) : "f"(x));
    return __uint_as_float(u);
}
__device__ __forceinline__ uint32_t smem_u32(const void* p) {
    uint32_t a;
    asm("{ .reg .u64 t; cvta.to.shared.u64 t, %1; cvt.u32.u64 %0, t; }"
        : "=r"(a) : "l"(p));
    return a;
}
__device__ __forceinline__ void cp16(uint32_t daddr, const float* src) {
    asm volatile("cp.async.cg.shared.global [%0], [%1], 16;"
                 :: "r"(daddr), "l"(src));
}
__device__ __forceinline__ void mma_tf32(
    float& d0, float& d1, float& d2, float& d3,
    uint32_t a0, uint32_t a1, uint32_t a2, uint32_t a3,
    uint32_t b0, uint32_t b1)
{
    asm volatile(
        "mma.sync.aligned.m16n8k8.row.col.f32.tf32.tf32.f32 "
        "{%0,%1,%2,%3}, {%4,%5,%6,%7}, {%8,%9}, {%0,%1,%2,%3};"
        : "+f"(d0), "+f"(d1), "+f"(d2), "+f"(d3)
        : "r"(a0), "r"(a1), "r"(a2), "r"(a3), "r"(b0), "r"(b1));
}

// ---------------------------------------------------------------------------
// Kernel 0: W3 -> fragment-ordered tf32 W3T.
// element idx = ((rb*12 + j)*32 + lane)*16 + (ks*2 + half)
//   holds B[n=j*8+g][k=ks*8+q+half*4] for n = rloc*32+o, r = rb*3+rloc.
// ---------------------------------------------------------------------------
__global__ __launch_bounds__(256) void k_w3t(const float* __restrict__ W3) {
    int e = blockIdx.x * 256 + threadIdx.x;       // 0 .. 196607
    int pos  = e & 15;
    int lane = (e >> 4) & 31;
    int t    = e >> 9;                            // rb*12 + j
    int j = t % 12, rb = t / 12;
    int g = lane >> 2, q = lane & 3;
    int ks = pos >> 1, half = pos & 1;
    int n = j * 8 + g;
    int rloc = n >> 5, o = n & 31;
    int k = ks * 8 + q + half * 4;
    g_W3T[e] = tf32_rna(W3[k * RAD_OUT + o * 96 + rb * 3 + rloc]);
}

// ---------------------------------------------------------------------------
// Kernel 1: radial MLP (layers 1-2) + per-edge feats@basis.
// One warp per TWO edges (2x ILP, CSE'd weight LDS); 16 edges / 256-thr block.
// ---------------------------------------------------------------------------
__global__ __launch_bounds__(256) void k_mlp(
    const float* __restrict__ edges, const float* __restrict__ feats,
    const float* __restrict__ basis,
    const float* __restrict__ W1, const float* __restrict__ b1,
    const float* __restrict__ g1, const float* __restrict__ be1,
    const float* __restrict__ W2, const float* __restrict__ b2,
    const float* __restrict__ g2, const float* __restrict__ be2)
{
    __shared__ float W1s[EDGE_D * MID_D];
    __shared__ float W2s[MID_D * MID_D];
    __shared__ float b1s[64], g1s[64], be1s[64], b2s[64], g2s[64], be2s[64];

    int tid = threadIdx.x;
    for (int i = tid; i < EDGE_D * MID_D; i += 256) W1s[i] = W1[i];
    for (int i = tid; i < MID_D * MID_D; i += 256) W2s[i] = W2[i];
    if (tid < 64) {
        b1s[tid] = b1[tid]; g1s[tid] = g1[tid]; be1s[tid] = be1[tid];
        b2s[tid] = b2[tid]; g2s[tid] = g2[tid]; be2s[tid] = be2[tid];
    }
    __syncthreads();

    int warp = tid >> 5, lane = tid & 31;
    int eA = blockIdx.x * 16 + warp * 2, eB = eA + 1;

    float xA = edges[eA * EDGE_D + lane];
    float xB = edges[eB * EDGE_D + lane];
    float a0A = b1s[lane], a1A = b1s[lane + 32];
    float a0B = a0A, a1B = a1A;
#pragma unroll
    for (int i = 0; i < 32; i++) {
        float wlo = W1s[i * 64 + lane], whi = W1s[i * 64 + 32 + lane];
        float xiA = __shfl_sync(0xffffffffu, xA, i);
        float xiB = __shfl_sync(0xffffffffu, xB, i);
        a0A = fmaf(xiA, wlo, a0A); a1A = fmaf(xiA, whi, a1A);
        a0B = fmaf(xiB, wlo, a0B); a1B = fmaf(xiB, whi, a1B);
    }
    {
        float mA = warp_sum(a0A + a1A) * (1.0f / 64.0f);
        float mB = warp_sum(a0B + a1B) * (1.0f / 64.0f);
        float d0A = a0A - mA, d1A = a1A - mA;
        float d0B = a0B - mB, d1B = a1B - mB;
        float vA = warp_sum(d0A * d0A + d1A * d1A) * (1.0f / 64.0f);
        float vB = warp_sum(d0B * d0B + d1B * d1B) * (1.0f / 64.0f);
        float iA = rsqrtf(vA + 1e-5f), iB = rsqrtf(vB + 1e-5f);
        a0A = gelu_exact(d0A * iA * g1s[lane]      + be1s[lane]);
        a1A = gelu_exact(d1A * iA * g1s[lane + 32] + be1s[lane + 32]);
        a0B = gelu_exact(d0B * iB * g1s[lane]      + be1s[lane]);
        a1B = gelu_exact(d1B * iB * g1s[lane + 32] + be1s[lane + 32]);
    }

    float c0A = b2s[lane], c1A = b2s[lane + 32];
    float c0B = c0A, c1B = c1A;
#pragma unroll
    for (int i = 0; i < 32; i++) {
        float wlo = W2s[i * 64 + lane], whi = W2s[i * 64 + 32 + lane];
        float xiA = __shfl_sync(0xffffffffu, a0A, i);
        float xiB = __shfl_sync(0xffffffffu, a0B, i);
        c0A = fmaf(xiA, wlo, c0A); c1A = fmaf(xiA, whi, c1A);
        c0B = fmaf(xiB, wlo, c0B); c1B = fmaf(xiB, whi, c1B);
    }
#pragma unroll
    for (int i = 0; i < 32; i++) {
        float wlo = W2s[(i + 32) * 64 + lane], whi = W2s[(i + 32) * 64 + 32 + lane];
        float xiA = __shfl_sync(0xffffffffu, a1A, i);
        float xiB = __shfl_sync(0xffffffffu, a1B, i);
        c0A = fmaf(xiA, wlo, c0A); c1A = fmaf(xiA, whi, c1A);
        c0B = fmaf(xiB, wlo, c0B); c1B = fmaf(xiB, whi, c1B);
    }
    {
        float mA = warp_sum(c0A + c1A) * (1.0f / 64.0f);
        float mB = warp_sum(c0B + c1B) * (1.0f / 64.0f);
        float d0A = c0A - mA, d1A = c1A - mA;
        float d0B = c0B - mB, d1B = c1B - mB;
        float vA = warp_sum(d0A * d0A + d1A * d1A) * (1.0f / 64.0f);
        float vB = warp_sum(d0B * d0B + d1B * d1B) * (1.0f / 64.0f);
        float iA = rsqrtf(vA + 1e-5f), iB = rsqrtf(vB + 1e-5f);
        c0A = gelu_exact(d0A * iA * g2s[lane]      + be2s[lane]);
        c1A = gelu_exact(d1A * iA * g2s[lane + 32] + be2s[lane + 32]);
        c0B = gelu_exact(d0B * iB * g2s[lane]      + be2s[lane]);
        c1B = gelu_exact(d1B * iB * g2s[lane + 32] + be2s[lane + 32]);
    }

    g_h2[eA * MID_D + lane]      = tf32_rna(c0A);
    g_h2[eA * MID_D + 32 + lane] = tf32_rna(c1A);
    g_h2[eB * MID_D + lane]      = tf32_rna(c0B);
    g_h2[eB * MID_D + 32 + lane] = tf32_rna(c1B);

    // tmp[e][rb=lane][rl*4 + m]: each rl triple 16B-aligned (4th = 0)
#pragma unroll
    for (int s = 0; s < 2; s++) {
        int e = s ? eB : eA;
        float f0 = feats[e * 96 + lane * 3 + 0];
        float f1 = feats[e * 96 + lane * 3 + 1];
        float f2 = feats[e * 96 + lane * 3 + 2];
        const float* bs = basis + e * 27;
        float v[9];
#pragma unroll
        for (int c = 0; c < 9; c++)
            v[c] = fmaf(f0, bs[c], fmaf(f1, bs[9 + c], f2 * bs[18 + c]));
        float4* tp = (float4*)(g_tmp + (size_t)e * 384 + lane * 12);
        tp[0] = make_float4(v[0], v[1], v[2], 0.0f);
        tp[1] = make_float4(v[3], v[4], v[5], 0.0f);
        tp[2] = make_float4(v[6], v[7], v[8], 0.0f);
    }
}

// ---------------------------------------------------------------------------
// Kernel 2: tf32 mma.sync GEMM + fused contraction, cp.async double-buffered B.
// CTA = 256 edges, 256 threads = 8 warps x 32 edges (M=32/warp: each B
// fragment feeds TWO m16 tiles -> B LDS per MAC halved vs M=16).
// Per rb: D(32x96/warp) = A(32x64) @ B_rb(96x64)^T; fold into 96 persistent
// per-thread accumulators (4 edge-slots x 8 o x 3 m) with tmp slices.
// ---------------------------------------------------------------------------
__global__ void __launch_bounds__(256, 1) k_main(float* __restrict__ out)
{
    extern __shared__ float Bs[];   // 2 * BBUF floats (61440 B)
    int tid = threadIdx.x, w = tid >> 5, lane = tid & 31;
    int g = lane >> 2, q = lane & 3;
    int ew = blockIdx.x * 256 + w * 32;
    uint32_t sb = smem_u32(Bs);

    // prologue: prefetch rb=0 into stage 0 (dst = (c>>2)*BSTRIDE + (c&3)*4)
#pragma unroll
    for (int i = 0; i < 6; i++) {
        int c = tid + 256 * i;
        cp16(sb + (((c >> 2) * BSTRIDE + (c & 3) * 4) << 2), g_W3T + c * 4);
    }
    asm volatile("cp.async.commit_group;" ::: "memory");

    // A fragments for 2 m16 tiles (rows ew+{0..15}, ew+{16..31}); persist
    uint32_t a[8][8];
    {
        const float* A0 = g_h2 + (size_t)(ew + g) * MID_D;
#pragma unroll
        for (int ks = 0; ks < 8; ks++) {
            a[ks][0] = __float_as_uint(A0[ks * 8 + q]);
            a[ks][1] = __float_as_uint(A0[8 * MID_D + ks * 8 + q]);
            a[ks][2] = __float_as_uint(A0[ks * 8 + q + 4]);
            a[ks][3] = __float_as_uint(A0[8 * MID_D + ks * 8 + q + 4]);
            a[ks][4] = __float_as_uint(A0[16 * MID_D + ks * 8 + q]);
            a[ks][5] = __float_as_uint(A0[24 * MID_D + ks * 8 + q]);
            a[ks][6] = __float_as_uint(A0[16 * MID_D + ks * 8 + q + 4]);
            a[ks][7] = __float_as_uint(A0[24 * MID_D + ks * 8 + q + 4]);
        }
    }

    float acc[4][8][3];
#pragma unroll
    for (int s = 0; s < 4; s++)
#pragma unroll
        for (int i = 0; i < 8; i++)
#pragma unroll
            for (int m = 0; m < 3; m++) acc[s][i][m] = 0.0f;

    const float4* tp0 = (const float4*)g_tmp + (size_t)(ew + g) * 96;
    const float4* tp1 = (const float4*)g_tmp + (size_t)(ew + g + 8) * 96;
    const float4* tp2 = (const float4*)g_tmp + (size_t)(ew + g + 16) * 96;
    const float4* tp3 = (const float4*)g_tmp + (size_t)(ew + g + 24) * 96;

    for (int rb = 0; rb < 32; rb++) {
        asm volatile("cp.async.wait_group 0;" ::: "memory");
        __syncthreads();                 // stage rb visible; other buf free
        if (rb < 31) {
            const float* src = g_W3T + (rb + 1) * 6144;
            uint32_t dbase = sb + ((rb + 1) & 1) * (BBUF * 4);
#pragma unroll
            for (int i = 0; i < 6; i++) {
                int c = tid + 256 * i;
                cp16(dbase + (((c >> 2) * BSTRIDE + (c & 3) * 4) << 2),
                     src + c * 4);
            }
            asm volatile("cp.async.commit_group;" ::: "memory");
        }

        const float* bbase = Bs + (rb & 1) * BBUF;
#pragma unroll
        for (int rl = 0; rl < 3; rl++) {
            float4 t0 = tp0[rb * 3 + rl], t1 = tp1[rb * 3 + rl];
            float4 t2 = tp2[rb * 3 + rl], t3 = tp3[rb * 3 + rl];
#pragma unroll
            for (int jm = 0; jm < 4; jm++) {
                int j = rl * 4 + jm;
                const float4* bp =
                    (const float4*)(bbase + (j * 32 + lane) * BSTRIDE);
                float4 f0 = bp[0], f1 = bp[1], f2 = bp[2], f3 = bp[3];
                uint32_t bf[16] = {
                    __float_as_uint(f0.x), __float_as_uint(f0.y),
                    __float_as_uint(f0.z), __float_as_uint(f0.w),
                    __float_as_uint(f1.x), __float_as_uint(f1.y),
                    __float_as_uint(f1.z), __float_as_uint(f1.w),
                    __float_as_uint(f2.x), __float_as_uint(f2.y),
                    __float_as_uint(f2.z), __float_as_uint(f2.w),
                    __float_as_uint(f3.x), __float_as_uint(f3.y),
                    __float_as_uint(f3.z), __float_as_uint(f3.w)};

                // tile0 (edges ew..ew+15): 2 chains of 4
                float d0 = 0.f, d1 = 0.f, d2 = 0.f, d3 = 0.f;
                float u0 = 0.f, u1 = 0.f, u2 = 0.f, u3 = 0.f;
                // tile1 (edges ew+16..ew+31)
                float p0 = 0.f, p1 = 0.f, p2 = 0.f, p3 = 0.f;
                float v0 = 0.f, v1 = 0.f, v2 = 0.f, v3 = 0.f;
#pragma unroll
                for (int ks = 0; ks < 8; ks += 2) {
                    mma_tf32(d0, d1, d2, d3,
                             a[ks][0], a[ks][1], a[ks][2], a[ks][3],
                             bf[ks * 2], bf[ks * 2 + 1]);
                    mma_tf32(p0, p1, p2, p3,
                             a[ks][4], a[ks][5], a[ks][6], a[ks][7],
                             bf[ks * 2], bf[ks * 2 + 1]);
                    mma_tf32(u0, u1, u2, u3,
                             a[ks + 1][0], a[ks + 1][1], a[ks + 1][2], a[ks + 1][3],
                             bf[ks * 2 + 2], bf[ks * 2 + 3]);
                    mma_tf32(v0, v1, v2, v3,
                             a[ks + 1][4], a[ks + 1][5], a[ks + 1][6], a[ks + 1][7],
                             bf[ks * 2 + 2], bf[ks * 2 + 3]);
                }
                d0 += u0; d1 += u1; d2 += u2; d3 += u3;
                p0 += v0; p1 += v1; p2 += v2; p3 += v3;

                int c0 = jm * 2, c1 = jm * 2 + 1;
                acc[0][c0][0] = fmaf(d0, t0.x, acc[0][c0][0]);
                acc[0][c0][1] = fmaf(d0, t0.y, acc[0][c0][1]);
                acc[0][c0][2] = fmaf(d0, t0.z, acc[0][c0][2]);
                acc[0][c1][0] = fmaf(d1, t0.x, acc[0][c1][0]);
                acc[0][c1][1] = fmaf(d1, t0.y, acc[0][c1][1]);
                acc[0][c1][2] = fmaf(d1, t0.z, acc[0][c1][2]);
                acc[1][c0][0] = fmaf(d2, t1.x, acc[1][c0][0]);
                acc[1][c0][1] = fmaf(d2, t1.y, acc[1][c0][1]);
                acc[1][c0][2] = fmaf(d2, t1.z, acc[1][c0][2]);
                acc[1][c1][0] = fmaf(d3, t1.x, acc[1][c1][0]);
                acc[1][c1][1] = fmaf(d3, t1.y, acc[1][c1][1]);
                acc[1][c1][2] = fmaf(d3, t1.z, acc[1][c1][2]);
                acc[2][c0][0] = fmaf(p0, t2.x, acc[2][c0][0]);
                acc[2][c0][1] = fmaf(p0, t2.y, acc[2][c0][1]);
                acc[2][c0][2] = fmaf(p0, t2.z, acc[2][c0][2]);
                acc[2][c1][0] = fmaf(p1, t2.x, acc[2][c1][0]);
                acc[2][c1][1] = fmaf(p1, t2.y, acc[2][c1][1]);
                acc[2][c1][2] = fmaf(p1, t2.z, acc[2][c1][2]);
                acc[3][c0][0] = fmaf(p2, t3.x, acc[3][c0][0]);
                acc[3][c0][1] = fmaf(p2, t3.y, acc[3][c0][1]);
                acc[3][c0][2] = fmaf(p2, t3.z, acc[3][c0][2]);
                acc[3][c1][0] = fmaf(p3, t3.x, acc[3][c1][0]);
                acc[3][c1][1] = fmaf(p3, t3.y, acc[3][c1][1]);
                acc[3][c1][2] = fmaf(p3, t3.z, acc[3][c1][2]);
            }
        }
    }

    // Store: slot s -> edge ew + g + s*8; o = jm*8 + 2q (+1)
#pragma unroll
    for (int s = 0; s < 4; s++) {
        float* op = out + (size_t)(ew + g + s * 8) * 96;
#pragma unroll
        for (int jm = 0; jm < 4; jm++) {
            float* p = op + (jm * 8 + 2 * q) * 3;
            float2* p2 = (float2*)p;
            p2[0] = make_float2(acc[s][jm * 2][0],     acc[s][jm * 2][1]);
            p2[1] = make_float2(acc[s][jm * 2][2],     acc[s][jm * 2 + 1][0]);
            p2[2] = make_float2(acc[s][jm * 2 + 1][1], acc[s][jm * 2 + 1][2]);
        }
    }
}

// ---------------------------------------------------------------------------
extern "C" void kernel_launch(void* const* d_in, const int* in_sizes, int n_in,
                              void* d_out, int out_size)
{
    const float* edges = (const float*)d_in[0];
    const float* feats = (const float*)d_in[1];
    const float* basis = (const float*)d_in[2];
    const float* W1    = (const float*)d_in[3];
    const float* b1    = (const float*)d_in[4];
    const float* g1    = (const float*)d_in[5];
    const float* be1   = (const float*)d_in[6];
    const float* W2    = (const float*)d_in[7];
    const float* b2    = (const float*)d_in[8];
    const float* g2    = (const float*)d_in[9];
    const float* be2   = (const float*)d_in[10];
    const float* W3    = (const float*)d_in[11];
    float* out = (float*)d_out;

    // Host-side attributes (not stream ops; capture-safe, no allocation)
    cudaFuncSetAttribute(k_main, cudaFuncAttributeMaxDynamicSharedMemorySize,
                         2 * BBUF * 4);
    cudaFuncSetAttribute(k_main,
                         cudaFuncAttributePreferredSharedMemoryCarveout, 100);

    k_w3t<<<(RAD_OUT * MID_D) / 256, 256>>>(W3);
    k_mlp<<<E_TOT / 16, 256>>>(edges, feats, basis, W1, b1, g1, be1,
                               W2, b2, g2, be2);
    k_main<<<E_TOT / 256, 256, 2 * BBUF * 4>>>(out);
}